// round 16
// baseline (speedup 1.0000x reference)
#include <cuda_runtime.h>
#include <cuda_fp16.h>
#include <cstdint>

#define SEQ 4096
#define DIM 1024
typedef __half fp16;

// ---------------- scratch ----------------
__device__ __align__(256) fp16 g_xqh[SEQ*DIM];
__device__ __align__(256) fp16 g_xkh[SEQ*DIM];
__device__ __align__(256) fp16 g_xvh[SEQ*DIM];
__device__ __align__(256) fp16 g_WqTh[DIM*DIM];
__device__ __align__(256) fp16 g_WkTh[DIM*DIM];
__device__ __align__(256) fp16 g_WvTh[DIM*DIM];
__device__ __align__(256) fp16 g_Qh[SEQ*DIM];
__device__ __align__(256) fp16 g_Kh[SEQ*DIM];
__device__ __align__(256) fp16 g_VTh[(size_t)DIM*SEQ];
__device__ __align__(256) fp16 g_VTs[(size_t)DIM*SEQ];
__device__ __align__(256) fp16 g_F[(size_t)SEQ*SEQ];
__device__ float g_r[SEQ];
__device__ float g_t[DIM];
__device__ float g_cs[DIM];

// ---------------- helpers ----------------
__device__ __forceinline__ uint32_t smem_u32(const void* p) {
    uint32_t a;
    asm("{ .reg .u64 t; cvta.to.shared.u64 t, %1; cvt.u32.u64 %0, t; }" : "=r"(a) : "l"(p));
    return a;
}
__device__ __forceinline__ void cp16(uint32_t s, const void* g) {
    asm volatile("cp.async.cg.shared.global [%0], [%1], 16;" :: "r"(s), "l"(g) : "memory");
}
#define CP_COMMIT() asm volatile("cp.async.commit_group;" ::: "memory")
#define CP_WAIT1()  asm volatile("cp.async.wait_group 1;" ::: "memory")
#define CP_WAIT0()  asm volatile("cp.async.wait_group 0;" ::: "memory")

__device__ __forceinline__ void mma_f16(float* c, const uint32_t* a, const uint32_t* b) {
    asm volatile(
        "mma.sync.aligned.m16n8k16.row.col.f32.f16.f16.f32 "
        "{%0,%1,%2,%3}, {%4,%5,%6,%7}, {%8,%9}, {%0,%1,%2,%3};"
        : "+f"(c[0]), "+f"(c[1]), "+f"(c[2]), "+f"(c[3])
        : "r"(a[0]), "r"(a[1]), "r"(a[2]), "r"(a[3]), "r"(b[0]), "r"(b[1]));
}
__device__ __forceinline__ void ldsm_x4(uint32_t* r, uint32_t addr) {
    asm volatile("ldmatrix.sync.aligned.m8n8.x4.shared.b16 {%0,%1,%2,%3}, [%4];"
        : "=r"(r[0]), "=r"(r[1]), "=r"(r[2]), "=r"(r[3]) : "r"(addr));
}

// expm1(x) for |x| < ~0.7: degree-6 Taylor, Horner. abs err < 1e-5.
__device__ __forceinline__ float expm1_poly(float x) {
    float p = 1.0f / 720.0f;
    p = fmaf(p, x, 1.0f / 120.0f);
    p = fmaf(p, x, 1.0f / 24.0f);
    p = fmaf(p, x, 1.0f / 6.0f);
    p = fmaf(p, x, 0.5f);
    p = fmaf(p, x, 1.0f);
    return x * p;
}

// ---------------------------------------------------------------------------
// Shared mainloop: 128x128 block tile, BK=64, 256 thr (8 warps 4x2, 32x64
// warp tiles), 3-stage cp.async, ONE __syncthreads per k-tile, 2 CTAs/SM.
// 4 warps/SMSP across 2 independent barrier domains -> tensor-pipe fill.
// ---------------------------------------------------------------------------
#define STRIDE 144
#define STAGE_BYTES (256 * STRIDE)           // 36864
#define SMEM_DYN (3 * STAGE_BYTES)           // 110592

template <int KP>
__device__ __forceinline__ void run_mainloop(
    const fp16* __restrict__ A0, const fp16* __restrict__ B0,
    uint32_t sb, size_t bm, size_t bn, float (&acc)[2][8][4])
{
    const int tid = threadIdx.x;
    const int warp = tid >> 5, lane = tid & 31;
    const int wm = warp & 3, wn = warp >> 2;      // 4 x 2 warp grid
    constexpr int ktot = KP / 64;

    const int lrow = tid >> 1;                    // 0..127
    const int lch  = (tid & 1) * 64;

    auto load_stage = [&](int buf, int kt) {
        const char* ag = (const char*)(A0 + (bm + lrow) * KP) + kt * 128 + lch;
        const char* bg = (const char*)(B0 + (bn + lrow) * KP) + kt * 128 + lch;
        uint32_t sa  = sb + buf * STAGE_BYTES + lrow * STRIDE + lch;
        uint32_t sbB = sa + 128 * STRIDE;
#pragma unroll
        for (int i = 0; i < 4; i++) cp16(sa  + i * 16, ag + i * 16);
#pragma unroll
        for (int i = 0; i < 4; i++) cp16(sbB + i * 16, bg + i * 16);
    };

#pragma unroll
    for (int mi = 0; mi < 2; mi++)
#pragma unroll
        for (int nj = 0; nj < 8; nj++)
#pragma unroll
            for (int q = 0; q < 4; q++) acc[mi][nj][q] = 0.0f;

    load_stage(0, 0); CP_COMMIT();
    load_stage(1, 1); CP_COMMIT();

    const uint32_t aOff = (uint32_t)(wm * 32 + (lane & 15)) * STRIDE + ((lane >> 4) << 4);
    const uint32_t bOff = (uint32_t)(wn * 64 + (lane & 7) + ((lane >> 4) & 1) * 8) * STRIDE
                          + (((lane >> 3) & 1) << 4);

    int buf = 0;
    for (int kt = 0; kt < ktot; kt++) {
        if (kt + 1 < ktot) CP_WAIT1(); else CP_WAIT0();
        __syncthreads();                         // single barrier per k-tile
        if (kt + 2 < ktot) {                     // stage (kt+2)%3 last read in
            load_stage((kt + 2) % 3, kt + 2);    // iter kt-1, protected above
            CP_COMMIT();
        }
        const uint32_t sA = sb + buf * STAGE_BYTES;
        const uint32_t sB = sA + 128 * STRIDE;
#pragma unroll
        for (int ks = 0; ks < 4; ks++) {
            uint32_t a[2][4], b[4][4];
#pragma unroll
            for (int mi = 0; mi < 2; mi++)
                ldsm_x4(a[mi], sA + aOff + mi * (16 * STRIDE) + ks * 32);
#pragma unroll
            for (int ni = 0; ni < 4; ni++)
                ldsm_x4(b[ni], sB + bOff + ni * (16 * STRIDE) + ks * 32);
#pragma unroll
            for (int mi = 0; mi < 2; mi++)
#pragma unroll
                for (int ni = 0; ni < 4; ni++) {
                    mma_f16(acc[mi][ni * 2],     a[mi], &b[ni][0]);
                    mma_f16(acc[mi][ni * 2 + 1], a[mi], &b[ni][2]);
                }
        }
        buf = (buf + 1) % 3;
    }
}

// ---------------- merged Q/K/V projection (z selects operand set) ----------
__global__ void __launch_bounds__(256, 2)
gemm_proj(const fp16* __restrict__ Aq, const fp16* __restrict__ Bq,
          const float* __restrict__ bq, fp16* __restrict__ Cq,
          const fp16* __restrict__ Ak, const fp16* __restrict__ Bk,
          const float* __restrict__ bk, fp16* __restrict__ Ck,
          const fp16* __restrict__ Av, const fp16* __restrict__ Bv,
          const float* __restrict__ bv, fp16* __restrict__ Cv)
{
    extern __shared__ char smem[];
    const uint32_t sb = smem_u32(smem);
    const int z = blockIdx.z;
    const fp16* A = (z == 0) ? Aq : (z == 1) ? Ak : Av;
    const fp16* B = (z == 0) ? Bq : (z == 1) ? Bk : Bv;
    const float* bias = (z == 0) ? bq : (z == 1) ? bk : bv;
    fp16* C = (z == 0) ? Cq : (z == 1) ? Ck : Cv;
    const size_t bm = (z == 2) ? (size_t)blockIdx.x * 128 : (size_t)blockIdx.y * 128;
    const size_t bn = (z == 2) ? (size_t)blockIdx.y * 128 : (size_t)blockIdx.x * 128;
    const int ldc = (z == 2) ? SEQ : DIM;

    float acc[2][8][4];
    run_mainloop<DIM>(A, B, sb, bm, bn, acc);

    const int warp = threadIdx.x >> 5, lane = threadIdx.x & 31;
    const int wm = warp & 3, wn = warp >> 2;
    const int row0 = (int)bm + wm * 32 + (lane >> 2);
    const int col0 = (int)bn + wn * 64 + (lane & 3) * 2;
#pragma unroll
    for (int mi = 0; mi < 2; mi++) {
#pragma unroll
        for (int h = 0; h < 2; h++) {
            const int r = row0 + mi * 16 + h * 8;
            const float bm_b = (z == 2) ? bias[r] : 0.0f;
#pragma unroll
            for (int nj = 0; nj < 8; nj++) {
                const int c = col0 + nj * 8;
                float v0 = acc[mi][nj][h * 2 + 0];
                float v1 = acc[mi][nj][h * 2 + 1];
                if (z == 2) { v0 += bm_b; v1 += bm_b; }
                else        { v0 += bias[c]; v1 += bias[c + 1]; }
                *(__half2*)(C + (size_t)r * ldc + c) =
                    __halves2half2(__float2half(v0), __float2half(v1));
            }
        }
    }
}

// ---------------- F = expm1((Q@K^T)/1024) via poly, fused rowsum ------------
__global__ void __launch_bounds__(256, 2)
gemm_F(const fp16* __restrict__ Q, const fp16* __restrict__ K,
       float* __restrict__ Rp, fp16* __restrict__ F)
{
    extern __shared__ char smem[];
    const uint32_t sb = smem_u32(smem);
    const size_t bm = (size_t)blockIdx.y * 128, bn = (size_t)blockIdx.x * 128;

    float acc[2][8][4];
    run_mainloop<DIM>(Q, K, sb, bm, bn, acc);

    const int warp = threadIdx.x >> 5, lane = threadIdx.x & 31;
    const int wm = warp & 3, wn = warp >> 2;
    const int row0 = (int)bm + wm * 32 + (lane >> 2);
    const int col0 = (int)bn + wn * 64 + (lane & 3) * 2;
#pragma unroll
    for (int mi = 0; mi < 2; mi++) {
#pragma unroll
        for (int h = 0; h < 2; h++) {
            const int r = row0 + mi * 16 + h * 8;
            float rs = 0.0f;
#pragma unroll
            for (int nj = 0; nj < 8; nj++) {
                const int c = col0 + nj * 8;
                float v0 = expm1_poly(acc[mi][nj][h * 2 + 0] * (1.0f / 1024.0f));
                float v1 = expm1_poly(acc[mi][nj][h * 2 + 1] * (1.0f / 1024.0f));
                *(__half2*)(F + (size_t)r * SEQ + c) =
                    __halves2half2(__float2half(v0), __float2half(v1));
                rs += v0 + v1;
            }
            rs += __shfl_xor_sync(0xFFFFFFFFu, rs, 1);
            rs += __shfl_xor_sync(0xFFFFFFFFu, rs, 2);
            if ((lane & 3) == 0) atomicAdd(Rp + r, rs);
        }
    }
}

// ---------------- out = F @ V''^T / 4096 + cs ----------------
__global__ void __launch_bounds__(256, 2)
gemm_out(const fp16* __restrict__ F, const fp16* __restrict__ VTs,
         const float* __restrict__ cs, float* __restrict__ out)
{
    extern __shared__ char smem[];
    const uint32_t sb = smem_u32(smem);
    const size_t bm = (size_t)blockIdx.y * 128, bn = (size_t)blockIdx.x * 128;

    float acc[2][8][4];
    run_mainloop<SEQ>(F, VTs, sb, bm, bn, acc);

    const int warp = threadIdx.x >> 5, lane = threadIdx.x & 31;
    const int wm = warp & 3, wn = warp >> 2;
    const int row0 = (int)bm + wm * 32 + (lane >> 2);
    const int col0 = (int)bn + wn * 64 + (lane & 3) * 2;
#pragma unroll
    for (int mi = 0; mi < 2; mi++) {
#pragma unroll
        for (int h = 0; h < 2; h++) {
            const int r = row0 + mi * 16 + h * 8;
#pragma unroll
            for (int nj = 0; nj < 8; nj++) {
                const int c = col0 + nj * 8;
                *(float2*)(out + (size_t)r * DIM + c) = make_float2(
                    acc[mi][nj][h * 2 + 0] * (1.0f / 4096.0f) + cs[c],
                    acc[mi][nj][h * 2 + 1] * (1.0f / 4096.0f) + cs[c + 1]);
            }
        }
    }
}

// ---------------- merged prep: inputs->fp16, W->W^T fp16, zero accums -------
__global__ void prep_all(const float* __restrict__ q, const float* __restrict__ k,
                         const float* __restrict__ v,
                         const float* __restrict__ Wq, const float* __restrict__ Wk,
                         const float* __restrict__ Wv,
                         fp16* __restrict__ qh, fp16* __restrict__ kh,
                         fp16* __restrict__ vh,
                         fp16* __restrict__ TQ, fp16* __restrict__ TK,
                         fp16* __restrict__ TV,
                         float* __restrict__ r, float* __restrict__ t,
                         float* __restrict__ cs) {
    int bid = blockIdx.x;
    if (bid < 3 * 4096) {
        int set = bid >> 12, blk = bid & 4095;
        const float* X = (set == 0) ? q : (set == 1) ? k : v;
        fp16* H = (set == 0) ? qh : (set == 1) ? kh : vh;
        size_t i = ((size_t)blk * 256 + threadIdx.x) * 4;
        float4 val = *(const float4*)(X + i);
        *(__half2*)(H + i)     = __halves2half2(__float2half(val.x), __float2half(val.y));
        *(__half2*)(H + i + 2) = __halves2half2(__float2half(val.z), __float2half(val.w));
        if (set == 0) {
            if (blk < SEQ / 1024)
                *(float4*)(r + blk * 1024 + threadIdx.x * 4) = make_float4(0,0,0,0);
            if (blk == 4)
                *(float4*)(t + threadIdx.x * 4) = make_float4(0,0,0,0);
            if (blk == 5)
                *(float4*)(cs + threadIdx.x * 4) = make_float4(0,0,0,0);
        }
    } else {
        __shared__ float tt[32][33];
        int wb = bid - 3 * 4096;
        int set = wb >> 10, blk = wb & 1023;
        const float* W = (set == 0) ? Wq : (set == 1) ? Wk : Wv;
        fp16* TH = (set == 0) ? TQ : (set == 1) ? TK : TV;
        int n0 = (blk & 31) * 32, k0 = (blk >> 5) * 32;
        int tx = threadIdx.x & 31, ty = threadIdx.x >> 5;   // 32 x 8
        for (int rr = ty; rr < 32; rr += 8)
            tt[rr][tx] = W[(size_t)(k0 + rr) * DIM + n0 + tx];
        __syncthreads();
        for (int rr = ty; rr < 32; rr += 8)
            TH[(size_t)(n0 + rr) * DIM + (k0 + tx)] = __float2half(tt[tx][rr]);
    }
}

// ---------------- merged mid-kernel: scale (blocks 0..4095) + colsum_t ------
__global__ void mid_kernel(const fp16* __restrict__ VTh, const float* __restrict__ r,
                           fp16* __restrict__ VTs,
                           const float* __restrict__ value, float* __restrict__ t) {
    int bid = blockIdx.x;
    if (bid < 4096) {
        size_t i = ((size_t)bid * 256 + threadIdx.x) * 4;
        int j = (int)(i % SEQ);
        float4 rr = *(const float4*)(r + j);
        __half2 h0 = *(const __half2*)(VTh + i);
        __half2 h1 = *(const __half2*)(VTh + i + 2);
        float2 f0 = __half22float2(h0), f1 = __half22float2(h1);
        f0.x *= 4096.0f / (4096.0f + rr.x);
        f0.y *= 4096.0f / (4096.0f + rr.y);
        f1.x *= 4096.0f / (4096.0f + rr.z);
        f1.y *= 4096.0f / (4096.0f + rr.w);
        *(__half2*)(VTs + i)     = __halves2half2(__float2half(f0.x), __float2half(f0.y));
        *(__half2*)(VTs + i + 2) = __halves2half2(__float2half(f1.x), __float2half(f1.y));
    } else {
        __shared__ float rinv[128];
        int blk = bid - 4096;
        int dq = blk & 3, jq = blk >> 2;
        int d = dq * 256 + threadIdx.x;
        int j0 = jq * 128;
        if (threadIdx.x < 128) rinv[threadIdx.x] = 1.0f / (4096.0f + r[j0 + threadIdx.x]);
        __syncthreads();
        float s = 0.f;
#pragma unroll 4
        for (int j = 0; j < 128; j++)
            s += value[(size_t)(j0 + j) * DIM + d] * rinv[j];
        atomicAdd(t + d, s);
    }
}

// ---------------- cs[d] += sum_k t[k]*Wv[k][d] (+ bv[d]*s0, computed here) ---
__global__ void colsum_cs(const float* __restrict__ t, const float* __restrict__ Wv,
                          const float* __restrict__ bv, const float* __restrict__ r,
                          float* __restrict__ cs) {
    __shared__ float ts[128];
    __shared__ float s0sh;
    int d = blockIdx.x * 256 + threadIdx.x;
    int k0 = blockIdx.y * 128;
    if (threadIdx.x < 128) ts[threadIdx.x] = t[k0 + threadIdx.x];
    if (blockIdx.y == 0) {
        float s = 0.f;
        for (int i = threadIdx.x; i < SEQ; i += 256) s += 1.0f / (4096.0f + r[i]);
#pragma unroll
        for (int o = 16; o > 0; o >>= 1) s += __shfl_down_sync(0xFFFFFFFFu, s, o);
        __shared__ float sm[8];
        if ((threadIdx.x & 31) == 0) sm[threadIdx.x >> 5] = s;
        __syncthreads();
        if (threadIdx.x == 0) {
            float tot = 0.f;
#pragma unroll
            for (int w = 0; w < 8; w++) tot += sm[w];
            s0sh = tot;
        }
    }
    __syncthreads();
    float s = 0.f;
#pragma unroll 4
    for (int kk = 0; kk < 128; kk++)
        s += ts[kk] * Wv[(size_t)(k0 + kk) * DIM + d];
    if (blockIdx.y == 0) s += bv[d] * s0sh;
    atomicAdd(cs + d, s);
}

// ---------------- launch ----------------
extern "C" void kernel_launch(void* const* d_in, const int* in_sizes, int n_in,
                              void* d_out, int out_size) {
    const float* query = (const float*)d_in[0];
    const float* key   = (const float*)d_in[1];
    const float* value = (const float*)d_in[2];
    const float* Wq    = (const float*)d_in[3];
    const float* bq    = (const float*)d_in[4];
    const float* Wk    = (const float*)d_in[5];
    const float* bk    = (const float*)d_in[6];
    const float* Wv    = (const float*)d_in[7];
    const float* bv    = (const float*)d_in[8];
    float* out = (float*)d_out;

    fp16 *xqh,*xkh,*xvh,*WqTh,*WkTh,*WvTh,*Qh,*Kh,*VTh,*VTs,*F;
    float *r,*t,*cs;
    cudaGetSymbolAddress((void**)&xqh, g_xqh);
    cudaGetSymbolAddress((void**)&xkh, g_xkh);
    cudaGetSymbolAddress((void**)&xvh, g_xvh);
    cudaGetSymbolAddress((void**)&WqTh, g_WqTh);
    cudaGetSymbolAddress((void**)&WkTh, g_WkTh);
    cudaGetSymbolAddress((void**)&WvTh, g_WvTh);
    cudaGetSymbolAddress((void**)&Qh, g_Qh);
    cudaGetSymbolAddress((void**)&Kh, g_Kh);
    cudaGetSymbolAddress((void**)&VTh, g_VTh);
    cudaGetSymbolAddress((void**)&VTs, g_VTs);
    cudaGetSymbolAddress((void**)&F, g_F);
    cudaGetSymbolAddress((void**)&r, g_r);
    cudaGetSymbolAddress((void**)&t, g_t);
    cudaGetSymbolAddress((void**)&cs, g_cs);

    cudaFuncSetAttribute(gemm_proj, cudaFuncAttributeMaxDynamicSharedMemorySize, SMEM_DYN);
    cudaFuncSetAttribute(gemm_F,    cudaFuncAttributeMaxDynamicSharedMemorySize, SMEM_DYN);
    cudaFuncSetAttribute(gemm_out,  cudaFuncAttributeMaxDynamicSharedMemorySize, SMEM_DYN);

    // (0) all prep in one launch
    prep_all<<<3 * 4096 + 3 * 1024, 256>>>(query, key, value, Wq, Wk, Wv,
                                           xqh, xkh, xvh, WqTh, WkTh, WvTh, r, t, cs);

    // (1) Q,K,V projections in ONE launch
    gemm_proj<<<dim3(DIM/128, SEQ/128, 3), 256, SMEM_DYN>>>(
        xqh, WqTh, bq, Qh,
        xkh, WkTh, bk, Kh,
        WvTh, xvh, bv, VTh);

    // (2) F = expm1((Q@K^T)/1024), fused rowsum
    gemm_F<<<dim3(SEQ/128, SEQ/128), 256, SMEM_DYN>>>(Qh, Kh, r, F);

    // (3) V'' scaling + colsum_t in one launch
    mid_kernel<<<4096 + 128, 256>>>(VTh, r, VTs, value, t);

    // (4) cs = t @ Wv + bv*s0
    colsum_cs<<<dim3(DIM/256, DIM/128), 256>>>(t, Wv, bv, r, cs);

    // (5) out = F @ V'' / 4096 + cs
    gemm_out<<<dim3(DIM/128, SEQ/128), 256, SMEM_DYN>>>(F, VTs, cs, out);
}

// round 17
// speedup vs baseline: 1.4066x; 1.4066x over previous
#include <cuda_runtime.h>
#include <cuda_fp16.h>
#include <cstdint>

#define SEQ 4096
#define DIM 1024
typedef __half fp16;

// ---------------- scratch ----------------
__device__ __align__(256) fp16 g_xqh[SEQ*DIM];
__device__ __align__(256) fp16 g_xkh[SEQ*DIM];
__device__ __align__(256) fp16 g_xvh[SEQ*DIM];
__device__ __align__(256) fp16 g_WqTh[DIM*DIM];
__device__ __align__(256) fp16 g_WkTh[DIM*DIM];
__device__ __align__(256) fp16 g_WvTh[DIM*DIM];
__device__ __align__(256) fp16 g_Qh[SEQ*DIM];
__device__ __align__(256) fp16 g_Kh[SEQ*DIM];
__device__ __align__(256) fp16 g_VTh[(size_t)DIM*SEQ];
__device__ __align__(256) fp16 g_VTs[(size_t)DIM*SEQ];
__device__ __align__(256) fp16 g_F[(size_t)SEQ*SEQ];
__device__ float g_r[SEQ];
__device__ float g_t[DIM];
__device__ float g_cs[DIM];

// ---------------- helpers ----------------
__device__ __forceinline__ uint32_t smem_u32(const void* p) {
    uint32_t a;
    asm("{ .reg .u64 t; cvta.to.shared.u64 t, %1; cvt.u32.u64 %0, t; }" : "=r"(a) : "l"(p));
    return a;
}
__device__ __forceinline__ void cp16(uint32_t s, const void* g) {
    asm volatile("cp.async.cg.shared.global [%0], [%1], 16;" :: "r"(s), "l"(g) : "memory");
}
#define CP_COMMIT() asm volatile("cp.async.commit_group;" ::: "memory")
#define CP_WAIT1()  asm volatile("cp.async.wait_group 1;" ::: "memory")
#define CP_WAIT0()  asm volatile("cp.async.wait_group 0;" ::: "memory")

__device__ __forceinline__ void mma_f16(float* c, const uint32_t* a, const uint32_t* b) {
    asm volatile(
        "mma.sync.aligned.m16n8k16.row.col.f32.f16.f16.f32 "
        "{%0,%1,%2,%3}, {%4,%5,%6,%7}, {%8,%9}, {%0,%1,%2,%3};"
        : "+f"(c[0]), "+f"(c[1]), "+f"(c[2]), "+f"(c[3])
        : "r"(a[0]), "r"(a[1]), "r"(a[2]), "r"(a[3]), "r"(b[0]), "r"(b[1]));
}
__device__ __forceinline__ void ldsm_x4(uint32_t* r, uint32_t addr) {
    asm volatile("ldmatrix.sync.aligned.m8n8.x4.shared.b16 {%0,%1,%2,%3}, [%4];"
        : "=r"(r[0]), "=r"(r[1]), "=r"(r[2]), "=r"(r[3]) : "r"(addr));
}

// expm1(x) for |x| < ~0.7: degree-6 Taylor, Horner. abs err < 1e-5.
__device__ __forceinline__ float expm1_poly(float x) {
    float p = 1.0f / 720.0f;
    p = fmaf(p, x, 1.0f / 120.0f);
    p = fmaf(p, x, 1.0f / 24.0f);
    p = fmaf(p, x, 1.0f / 6.0f);
    p = fmaf(p, x, 0.5f);
    p = fmaf(p, x, 1.0f);
    return x * p;
}

// ---------------------------------------------------------------------------
// Shared mainloop (R14-validated optimum — DO NOT MODIFY):
// 128x128 block tile, BK=64, 128 thr (4 warps 2x2, 64x64 warp tiles),
// 3-stage cp.async, ONE __syncthreads per k-tile, 2 CTAs/SM.
// ---------------------------------------------------------------------------
#define STRIDE 144
#define STAGE_BYTES (256 * STRIDE)           // 36864
#define SMEM_DYN (3 * STAGE_BYTES)           // 110592

template <int KP>
__device__ __forceinline__ void run_mainloop(
    const fp16* __restrict__ A0, const fp16* __restrict__ B0,
    uint32_t sb, size_t bm, size_t bn, float (&acc)[4][8][4])
{
    const int tid = threadIdx.x;
    const int warp = tid >> 5, lane = tid & 31;
    const int wm = warp & 1, wn = warp >> 1;
    constexpr int ktot = KP / 64;

    const int lrow = tid >> 3;
    const int lch  = (tid & 7) * 16;

    auto load_stage = [&](int buf, int kt) {
        const char* ag = (const char*)(A0 + (bm + lrow) * KP) + kt * 128 + lch;
        const char* bg = (const char*)(B0 + (bn + lrow) * KP) + kt * 128 + lch;
        uint32_t sa  = sb + buf * STAGE_BYTES + lrow * STRIDE + lch;
        uint32_t sbB = sa + 128 * STRIDE;
#pragma unroll
        for (int i = 0; i < 8; i++)
            cp16(sa + i * (16 * STRIDE), ag + (size_t)i * (16 * KP * 2));
#pragma unroll
        for (int i = 0; i < 8; i++)
            cp16(sbB + i * (16 * STRIDE), bg + (size_t)i * (16 * KP * 2));
    };

#pragma unroll
    for (int mi = 0; mi < 4; mi++)
#pragma unroll
        for (int nj = 0; nj < 8; nj++)
#pragma unroll
            for (int q = 0; q < 4; q++) acc[mi][nj][q] = 0.0f;

    load_stage(0, 0); CP_COMMIT();
    load_stage(1, 1); CP_COMMIT();

    const uint32_t aOff = (uint32_t)(wm * 64 + (lane & 15)) * STRIDE + ((lane >> 4) << 4);
    const uint32_t bOff = (uint32_t)(wn * 64 + (lane & 7) + ((lane >> 4) & 1) * 8) * STRIDE
                          + (((lane >> 3) & 1) << 4);

    int buf = 0;
    for (int kt = 0; kt < ktot; kt++) {
        if (kt + 1 < ktot) CP_WAIT1(); else CP_WAIT0();
        __syncthreads();                         // single barrier per k-tile
        if (kt + 2 < ktot) {                     // stage (kt+2)%3 last read in
            load_stage((kt + 2) % 3, kt + 2);    // iter kt-1, protected above
            CP_COMMIT();
        }
        const uint32_t sA = sb + buf * STAGE_BYTES;
        const uint32_t sB = sA + 128 * STRIDE;
#pragma unroll
        for (int ks = 0; ks < 4; ks++) {
            uint32_t a[4][4], b[4][4];
#pragma unroll
            for (int mi = 0; mi < 4; mi++)
                ldsm_x4(a[mi], sA + aOff + mi * (16 * STRIDE) + ks * 32);
#pragma unroll
            for (int ni = 0; ni < 4; ni++)
                ldsm_x4(b[ni], sB + bOff + ni * (16 * STRIDE) + ks * 32);
#pragma unroll
            for (int mi = 0; mi < 4; mi++)
#pragma unroll
                for (int ni = 0; ni < 4; ni++) {
                    mma_f16(acc[mi][ni * 2],     a[mi], &b[ni][0]);
                    mma_f16(acc[mi][ni * 2 + 1], a[mi], &b[ni][2]);
                }
        }
        buf = (buf + 1) % 3;
    }
}

// ---------------- merged Q/K/V projection (z selects operand set) ----------
__global__ void __launch_bounds__(128, 2)
gemm_proj(const fp16* __restrict__ Aq, const fp16* __restrict__ Bq,
          const float* __restrict__ bq, fp16* __restrict__ Cq,
          const fp16* __restrict__ Ak, const fp16* __restrict__ Bk,
          const float* __restrict__ bk, fp16* __restrict__ Ck,
          const fp16* __restrict__ Av, const fp16* __restrict__ Bv,
          const float* __restrict__ bv, fp16* __restrict__ Cv)
{
    extern __shared__ char smem[];
    const uint32_t sb = smem_u32(smem);
    const int z = blockIdx.z;
    const fp16* A = (z == 0) ? Aq : (z == 1) ? Ak : Av;
    const fp16* B = (z == 0) ? Bq : (z == 1) ? Bk : Bv;
    const float* bias = (z == 0) ? bq : (z == 1) ? bk : bv;
    fp16* C = (z == 0) ? Cq : (z == 1) ? Ck : Cv;
    const size_t bm = (z == 2) ? (size_t)blockIdx.x * 128 : (size_t)blockIdx.y * 128;
    const size_t bn = (z == 2) ? (size_t)blockIdx.y * 128 : (size_t)blockIdx.x * 128;
    const int ldc = (z == 2) ? SEQ : DIM;

    float acc[4][8][4];
    run_mainloop<DIM>(A, B, sb, bm, bn, acc);

    const int warp = threadIdx.x >> 5, lane = threadIdx.x & 31;
    const int wm = warp & 1, wn = warp >> 1;
    const int row0 = (int)bm + wm * 64 + (lane >> 2);
    const int col0 = (int)bn + wn * 64 + (lane & 3) * 2;
#pragma unroll
    for (int mi = 0; mi < 4; mi++) {
#pragma unroll
        for (int h = 0; h < 2; h++) {
            const int r = row0 + mi * 16 + h * 8;
            const float bm_b = (z == 2) ? bias[r] : 0.0f;
#pragma unroll
            for (int nj = 0; nj < 8; nj++) {
                const int c = col0 + nj * 8;
                float v0 = acc[mi][nj][h * 2 + 0];
                float v1 = acc[mi][nj][h * 2 + 1];
                if (z == 2) { v0 += bm_b; v1 += bm_b; }
                else        { v0 += bias[c]; v1 += bias[c + 1]; }
                *(__half2*)(C + (size_t)r * ldc + c) =
                    __halves2half2(__float2half(v0), __float2half(v1));
            }
        }
    }
}

// ---------------- F = expm1((Q@K^T)/1024) via poly, fused rowsum ------------
__global__ void __launch_bounds__(128, 2)
gemm_F(const fp16* __restrict__ Q, const fp16* __restrict__ K,
       float* __restrict__ Rp, fp16* __restrict__ F)
{
    extern __shared__ char smem[];
    const uint32_t sb = smem_u32(smem);
    const size_t bm = (size_t)blockIdx.y * 128, bn = (size_t)blockIdx.x * 128;

    float acc[4][8][4];
    run_mainloop<DIM>(Q, K, sb, bm, bn, acc);

    const int warp = threadIdx.x >> 5, lane = threadIdx.x & 31;
    const int wm = warp & 1, wn = warp >> 1;
    const int row0 = (int)bm + wm * 64 + (lane >> 2);
    const int col0 = (int)bn + wn * 64 + (lane & 3) * 2;
#pragma unroll
    for (int mi = 0; mi < 4; mi++) {
#pragma unroll
        for (int h = 0; h < 2; h++) {
            const int r = row0 + mi * 16 + h * 8;
            float rs = 0.0f;
#pragma unroll
            for (int nj = 0; nj < 8; nj++) {
                const int c = col0 + nj * 8;
                float v0 = expm1_poly(acc[mi][nj][h * 2 + 0] * (1.0f / 1024.0f));
                float v1 = expm1_poly(acc[mi][nj][h * 2 + 1] * (1.0f / 1024.0f));
                *(__half2*)(F + (size_t)r * SEQ + c) =
                    __halves2half2(__float2half(v0), __float2half(v1));
                rs += v0 + v1;
            }
            rs += __shfl_xor_sync(0xFFFFFFFFu, rs, 1);
            rs += __shfl_xor_sync(0xFFFFFFFFu, rs, 2);
            if ((lane & 3) == 0) atomicAdd(Rp + r, rs);
        }
    }
}

// ---------------- out = F @ V''^T / 4096 + cs ----------------
__global__ void __launch_bounds__(128, 2)
gemm_out(const fp16* __restrict__ F, const fp16* __restrict__ VTs,
         const float* __restrict__ cs, float* __restrict__ out)
{
    extern __shared__ char smem[];
    const uint32_t sb = smem_u32(smem);
    const size_t bm = (size_t)blockIdx.y * 128, bn = (size_t)blockIdx.x * 128;

    float acc[4][8][4];
    run_mainloop<SEQ>(F, VTs, sb, bm, bn, acc);

    const int warp = threadIdx.x >> 5, lane = threadIdx.x & 31;
    const int wm = warp & 1, wn = warp >> 1;
    const int row0 = (int)bm + wm * 64 + (lane >> 2);
    const int col0 = (int)bn + wn * 64 + (lane & 3) * 2;
#pragma unroll
    for (int mi = 0; mi < 4; mi++) {
#pragma unroll
        for (int h = 0; h < 2; h++) {
            const int r = row0 + mi * 16 + h * 8;
#pragma unroll
            for (int nj = 0; nj < 8; nj++) {
                const int c = col0 + nj * 8;
                *(float2*)(out + (size_t)r * DIM + c) = make_float2(
                    acc[mi][nj][h * 2 + 0] * (1.0f / 4096.0f) + cs[c],
                    acc[mi][nj][h * 2 + 1] * (1.0f / 4096.0f) + cs[c + 1]);
            }
        }
    }
}

// ---------------- merged prep: inputs->fp16, W->W^T fp16, zero accums -------
__global__ void prep_all(const float* __restrict__ q, const float* __restrict__ k,
                         const float* __restrict__ v,
                         const float* __restrict__ Wq, const float* __restrict__ Wk,
                         const float* __restrict__ Wv,
                         fp16* __restrict__ qh, fp16* __restrict__ kh,
                         fp16* __restrict__ vh,
                         fp16* __restrict__ TQ, fp16* __restrict__ TK,
                         fp16* __restrict__ TV,
                         float* __restrict__ r, float* __restrict__ t,
                         float* __restrict__ cs) {
    int bid = blockIdx.x;
    if (bid < 3 * 4096) {
        int set = bid >> 12, blk = bid & 4095;
        const float* X = (set == 0) ? q : (set == 1) ? k : v;
        fp16* H = (set == 0) ? qh : (set == 1) ? kh : vh;
        size_t i = ((size_t)blk * 256 + threadIdx.x) * 4;
        float4 val = *(const float4*)(X + i);
        *(__half2*)(H + i)     = __halves2half2(__float2half(val.x), __float2half(val.y));
        *(__half2*)(H + i + 2) = __halves2half2(__float2half(val.z), __float2half(val.w));
        if (set == 0) {
            if (blk < SEQ / 1024)
                *(float4*)(r + blk * 1024 + threadIdx.x * 4) = make_float4(0,0,0,0);
            if (blk == 4)
                *(float4*)(t + threadIdx.x * 4) = make_float4(0,0,0,0);
            if (blk == 5)
                *(float4*)(cs + threadIdx.x * 4) = make_float4(0,0,0,0);
        }
    } else {
        __shared__ float tt[32][33];
        int wb = bid - 3 * 4096;
        int set = wb >> 10, blk = wb & 1023;
        const float* W = (set == 0) ? Wq : (set == 1) ? Wk : Wv;
        fp16* TH = (set == 0) ? TQ : (set == 1) ? TK : TV;
        int n0 = (blk & 31) * 32, k0 = (blk >> 5) * 32;
        int tx = threadIdx.x & 31, ty = threadIdx.x >> 5;   // 32 x 8
        for (int rr = ty; rr < 32; rr += 8)
            tt[rr][tx] = W[(size_t)(k0 + rr) * DIM + n0 + tx];
        __syncthreads();
        for (int rr = ty; rr < 32; rr += 8)
            TH[(size_t)(n0 + rr) * DIM + (k0 + tx)] = __float2half(tt[tx][rr]);
    }
}

// ---------------- merged mid-kernel: scale (uint4, 16B/thr) + colsum_t ------
// blocks [0, 2048)        : V''T[d][j] = VTh[d][j] * 4096/(4096+r[j])  (8 halves/thr)
// blocks [2048, 2048+128) : t[d] += sum_{j in blk} value[j][d]/(4096+r[j])
__global__ void mid_kernel(const fp16* __restrict__ VTh, const float* __restrict__ r,
                           fp16* __restrict__ VTs,
                           const float* __restrict__ value, float* __restrict__ t) {
    int bid = blockIdx.x;
    if (bid < 2048) {
        size_t i = ((size_t)bid * 256 + threadIdx.x) * 8;
        int j = (int)(i % SEQ);
        float4 r0 = *(const float4*)(r + j);
        float4 r1 = *(const float4*)(r + j + 4);
        uint4 hv = *(const uint4*)(VTh + i);
        const __half2* hp = (const __half2*)&hv;
        uint4 ov;
        __half2* op = (__half2*)&ov;
        float rs[8] = {4096.0f / (4096.0f + r0.x), 4096.0f / (4096.0f + r0.y),
                       4096.0f / (4096.0f + r0.z), 4096.0f / (4096.0f + r0.w),
                       4096.0f / (4096.0f + r1.x), 4096.0f / (4096.0f + r1.y),
                       4096.0f / (4096.0f + r1.z), 4096.0f / (4096.0f + r1.w)};
#pragma unroll
        for (int q = 0; q < 4; q++) {
            float2 f = __half22float2(hp[q]);
            op[q] = __halves2half2(__float2half(f.x * rs[q * 2]),
                                   __float2half(f.y * rs[q * 2 + 1]));
        }
        *(uint4*)(VTs + i) = ov;
    } else {
        __shared__ float rinv[128];
        int blk = bid - 2048;
        int dq = blk & 3, jq = blk >> 2;
        int d = dq * 256 + threadIdx.x;
        int j0 = jq * 128;
        if (threadIdx.x < 128) rinv[threadIdx.x] = 1.0f / (4096.0f + r[j0 + threadIdx.x]);
        __syncthreads();
        float s = 0.f;
#pragma unroll 4
        for (int j = 0; j < 128; j++)
            s += value[(size_t)(j0 + j) * DIM + d] * rinv[j];
        atomicAdd(t + d, s);
    }
}

// ---------------- cs[d] += sum_k t[k]*Wv[k][d] (+ bv[d]*s0, computed here) ---
// grid (DIM/256, DIM/32) = (4, 32): finer k-split for parallelism.
__global__ void colsum_cs(const float* __restrict__ t, const float* __restrict__ Wv,
                          const float* __restrict__ bv, const float* __restrict__ r,
                          float* __restrict__ cs) {
    __shared__ float ts[32];
    __shared__ float s0sh;
    int d = blockIdx.x * 256 + threadIdx.x;
    int k0 = blockIdx.y * 32;
    if (threadIdx.x < 32) ts[threadIdx.x] = t[k0 + threadIdx.x];
    if (blockIdx.y == 0) {
        float s = 0.f;
        for (int i = threadIdx.x; i < SEQ; i += 256) s += 1.0f / (4096.0f + r[i]);
#pragma unroll
        for (int o = 16; o > 0; o >>= 1) s += __shfl_down_sync(0xFFFFFFFFu, s, o);
        __shared__ float sm[8];
        if ((threadIdx.x & 31) == 0) sm[threadIdx.x >> 5] = s;
        __syncthreads();
        if (threadIdx.x == 0) {
            float tot = 0.f;
#pragma unroll
            for (int w = 0; w < 8; w++) tot += sm[w];
            s0sh = tot;
        }
    }
    __syncthreads();
    float s = 0.f;
#pragma unroll 8
    for (int kk = 0; kk < 32; kk++)
        s += ts[kk] * Wv[(size_t)(k0 + kk) * DIM + d];
    if (blockIdx.y == 0) s += bv[d] * s0sh;
    atomicAdd(cs + d, s);
}

// ---------------- launch ----------------
extern "C" void kernel_launch(void* const* d_in, const int* in_sizes, int n_in,
                              void* d_out, int out_size) {
    const float* query = (const float*)d_in[0];
    const float* key   = (const float*)d_in[1];
    const float* value = (const float*)d_in[2];
    const float* Wq    = (const float*)d_in[3];
    const float* bq    = (const float*)d_in[4];
    const float* Wk    = (const float*)d_in[5];
    const float* bk    = (const float*)d_in[6];
    const float* Wv    = (const float*)d_in[7];
    const float* bv    = (const float*)d_in[8];
    float* out = (float*)d_out;

    fp16 *xqh,*xkh,*xvh,*WqTh,*WkTh,*WvTh,*Qh,*Kh,*VTh,*VTs,*F;
    float *r,*t,*cs;
    cudaGetSymbolAddress((void**)&xqh, g_xqh);
    cudaGetSymbolAddress((void**)&xkh, g_xkh);
    cudaGetSymbolAddress((void**)&xvh, g_xvh);
    cudaGetSymbolAddress((void**)&WqTh, g_WqTh);
    cudaGetSymbolAddress((void**)&WkTh, g_WkTh);
    cudaGetSymbolAddress((void**)&WvTh, g_WvTh);
    cudaGetSymbolAddress((void**)&Qh, g_Qh);
    cudaGetSymbolAddress((void**)&Kh, g_Kh);
    cudaGetSymbolAddress((void**)&VTh, g_VTh);
    cudaGetSymbolAddress((void**)&VTs, g_VTs);
    cudaGetSymbolAddress((void**)&F, g_F);
    cudaGetSymbolAddress((void**)&r, g_r);
    cudaGetSymbolAddress((void**)&t, g_t);
    cudaGetSymbolAddress((void**)&cs, g_cs);

    cudaFuncSetAttribute(gemm_proj, cudaFuncAttributeMaxDynamicSharedMemorySize, SMEM_DYN);
    cudaFuncSetAttribute(gemm_F,    cudaFuncAttributeMaxDynamicSharedMemorySize, SMEM_DYN);
    cudaFuncSetAttribute(gemm_out,  cudaFuncAttributeMaxDynamicSharedMemorySize, SMEM_DYN);

    // (0) all prep in one launch
    prep_all<<<3 * 4096 + 3 * 1024, 256>>>(query, key, value, Wq, Wk, Wv,
                                           xqh, xkh, xvh, WqTh, WkTh, WvTh, r, t, cs);

    // (1) Q,K,V projections in ONE launch
    gemm_proj<<<dim3(DIM/128, SEQ/128, 3), 128, SMEM_DYN>>>(
        xqh, WqTh, bq, Qh,
        xkh, WkTh, bk, Kh,
        WvTh, xvh, bv, VTh);

    // (2) F = expm1((Q@K^T)/1024), fused rowsum
    gemm_F<<<dim3(SEQ/128, SEQ/128), 128, SMEM_DYN>>>(Qh, Kh, r, F);

    // (3) V'' scaling + colsum_t in one launch
    mid_kernel<<<2048 + 128, 256>>>(VTh, r, VTs, value, t);

    // (4) cs = t @ Wv + bv*s0
    colsum_cs<<<dim3(DIM/256, DIM/32), 256>>>(t, Wv, bv, r, cs);

    // (5) out = F @ V'' / 4096 + cs
    gemm_out<<<dim3(DIM/128, SEQ/128), 128, SMEM_DYN>>>(F, VTs, cs, out);
}